// round 2
// baseline (speedup 1.0000x reference)
#include <cuda_runtime.h>
#include <cstdint>
#include <cstddef>

#define TB   128   // batch
#define TT   512   // time steps
#define EE   256   // embedding dim
#define HH   256   // hidden dim
#define G4   1024  // 4*H gate width
#define VV   32000 // vocab
#define NCLS 32    // classes
#define NCTA 128   // persistent grid size (<=148 SMs -> co-resident guaranteed)

// ---- static device scratch (no allocations allowed) ----
__device__ float g_embW[(size_t)2 * VV * G4];   // [dir][V][4H]  = 262 MB
__device__ float g_hbuf[2 * 2 * TB * HH];       // [buf][dir][b][j] double-buffered h
__device__ int   g_arrive;                      // barrier arrival counter (returns to 0)
__device__ int   g_epoch;                       // barrier epoch (monotonic, base-relative)

__device__ __forceinline__ float sigm(float x) { return 1.0f / (1.0f + __expf(-x)); }

// ============================================================================
// Kernel 1: embW[d][v][g] = sum_e emb[v][e] * W_d[e][g]
// grid (V/32, 4, 2), block 256. Each block: 32 v-rows x 256 g-cols, K=256.
// ============================================================================
__global__ void __launch_bounds__(256) k_embW(const float* __restrict__ emb,
                                              const float* __restrict__ Wf,
                                              const float* __restrict__ Wb)
{
    __shared__ float she[256][36];   // [e][v] transposed, padded (36 KB)
    const int v0  = blockIdx.x * 32;
    const int gt  = blockIdx.y;
    const int d   = blockIdx.z;
    const int tid = threadIdx.x;
    const float* __restrict__ W = d ? Wb : Wf;

    for (int idx = tid; idx < 32 * 256; idx += 256) {
        int vl = idx >> 8, e = idx & 255;
        she[e][vl] = emb[(size_t)(v0 + vl) * EE + e];   // coalesced over e
    }
    __syncthreads();

    const int g = gt * 256 + tid;
    float acc[32];
#pragma unroll
    for (int r = 0; r < 32; ++r) acc[r] = 0.f;

    const float* __restrict__ Wg = W + g;
    for (int e = 0; e < 256; ++e) {
        float w = Wg[(size_t)e * G4];                   // coalesced 128B/warp
#pragma unroll
        for (int r8 = 0; r8 < 8; ++r8) {
            float4 a = *(const float4*)&she[e][r8 * 4]; // broadcast, 16B aligned
            acc[r8 * 4 + 0] = fmaf(a.x, w, acc[r8 * 4 + 0]);
            acc[r8 * 4 + 1] = fmaf(a.y, w, acc[r8 * 4 + 1]);
            acc[r8 * 4 + 2] = fmaf(a.z, w, acc[r8 * 4 + 2]);
            acc[r8 * 4 + 3] = fmaf(a.w, w, acc[r8 * 4 + 3]);
        }
    }
    size_t base = ((size_t)d * VV + v0) * G4 + g;
#pragma unroll
    for (int r = 0; r < 32; ++r) g_embW[base + (size_t)r * G4] = acc[r];
}

// ============================================================================
// Kernel 2: persistent bidirectional LSTM recurrence.
// Grid: 128 CTAs = 2 dirs x 8 b-tiles(16) x 8 j-tiles(32 strided gate cols).
// CTA owns the full i/f/g/o quadruple for its (b,j) cells -> c lives in smem,
// one grid barrier per step, h double-buffered in global.
// ============================================================================
__global__ void __launch_bounds__(256, 1) k_lstm(const void* __restrict__ tokens_raw,
                                                 const float* __restrict__ Uf,
                                                 const float* __restrict__ bf,
                                                 const float* __restrict__ Ub,
                                                 const float* __restrict__ bb)
{
    __shared__ float sh_h[256][20];  // [k][b] transposed h tile, padded (20 KB)
    __shared__ float sz[16][128];    // z gate tile [b][q*32+jj] (8 KB)
    __shared__ float sc[16][32];     // cell state, CTA-private (2 KB)

    const int id  = blockIdx.x;
    const int jt  = id & 7;
    const int bt  = (id >> 3) & 7;
    const int d   = id >> 6;
    const int tid = threadIdx.x;

    const float* __restrict__ U   = d ? Ub : Uf;
    const float* __restrict__ bia = d ? bb : bf;

    const int b0      = bt * 16;
    const int colbase = jt * 32;
    const int gl      = tid & 127;          // gate-local column 0..127 (q*32+jj)
    const int bh      = tid >> 7;           // batch half 0/1
    const int col     = colbase + (gl & 31) + ((gl >> 5) << 8); // global gate col
    const int bloc0   = bh * 8;

    // ---- runtime token dtype probe: int64 high words are all zero ----
    const int*       __restrict__ t32 = (const int*)tokens_raw;
    const long long* __restrict__ t64 = (const long long*)tokens_raw;
    int probe = 0;
#pragma unroll
    for (int i = 1; i < 64; i += 2) probe |= t32[i];
    const bool tok32 = (probe != 0);

    for (int idx = tid; idx < 512; idx += 256) sc[idx >> 5][idx & 31] = 0.f;
    const int epoch0 = *(volatile int*)&g_epoch;  // stable between launches
    __syncthreads();

    const float bcol = bia[col];
    const float* __restrict__ Ucol = U + col;

    for (int s = 0; s < TT; ++s) {
        const int tstep = d ? (TT - 1 - s) : s;
        float acc[8];
#pragma unroll
        for (int r = 0; r < 8; ++r) acc[r] = 0.f;

        if (s > 0) {   // h_0 = 0 -> skip recurrent GEMM at step 0
            const int rb = s & 1;   // step s-1 wrote buffer s&1
            const float* __restrict__ hsrc =
                g_hbuf + ((size_t)(rb * 2 + d) * TB + b0) * HH;
            for (int idx = tid; idx < 16 * 256; idx += 256) {
                int bl = idx >> 8, k = idx & 255;
                sh_h[k][bl] = hsrc[bl * HH + k];        // coalesced read
            }
            __syncthreads();
#pragma unroll 4
            for (int k = 0; k < 256; ++k) {
                float u = Ucol[(size_t)k * G4];          // 128B/warp, L1-reused
                float4 ha = *(const float4*)&sh_h[k][bloc0];
                float4 hb = *(const float4*)&sh_h[k][bloc0 + 4];
                acc[0] = fmaf(ha.x, u, acc[0]); acc[1] = fmaf(ha.y, u, acc[1]);
                acc[2] = fmaf(ha.z, u, acc[2]); acc[3] = fmaf(ha.w, u, acc[3]);
                acc[4] = fmaf(hb.x, u, acc[4]); acc[5] = fmaf(hb.y, u, acc[5]);
                acc[6] = fmaf(hb.z, u, acc[6]); acc[7] = fmaf(hb.w, u, acc[7]);
            }
        }

        // add gathered input projection + bias, stage z in shared
#pragma unroll
        for (int r = 0; r < 8; ++r) {
            int b  = b0 + bloc0 + r;
            int tk = tok32 ? t32[b * TT + tstep] : (int)t64[b * TT + tstep];
            float xw = g_embW[((size_t)d * VV + tk) * G4 + col];
            sz[bloc0 + r][gl] = acc[r] + xw + bcol;
        }
        __syncthreads();

        // gate update: 512 cells, 2 per thread; c stays in smem
#pragma unroll
        for (int half = 0; half < 2; ++half) {
            int cell = tid + half * 256;
            int bl = cell >> 5, jj = cell & 31;
            float zi = sz[bl][jj];
            float zf = sz[bl][32 + jj];
            float zg = sz[bl][64 + jj];
            float zo = sz[bl][96 + jj];
            float c  = sc[bl][jj];
            float cn = sigm(zf) * c + sigm(zi) * tanhf(zg);
            float h  = sigm(zo) * tanhf(cn);
            sc[bl][jj] = cn;
            g_hbuf[((size_t)(((s + 1) & 1) * 2 + d) * TB + (b0 + bl)) * HH
                   + colbase + jj] = h;
        }
        __syncthreads();

        // ---- grid barrier (sense/epoch; all 128 CTAs co-resident) ----
        if (tid == 0) {
            __threadfence();
            int a = atomicAdd(&g_arrive, 1);
            if (a == NCTA - 1) {
                atomicExch(&g_arrive, 0);
                __threadfence();
                atomicAdd(&g_epoch, 1);
            } else {
                const int target = epoch0 + s + 1;
                while ((*(volatile int*)&g_epoch) - target < 0) { }
            }
            __threadfence();
        }
        __syncthreads();
    }
}

// ============================================================================
// Kernel 3: head. One block per batch row.
// h_cat[512] -> relu(dense 256) -> logits 32 -> softmax.
// Final h lives in g_hbuf buffer (511+1)&1 = 0.
// ============================================================================
__global__ void __launch_bounds__(256) k_head(const float* __restrict__ W1,
                                              const float* __restrict__ b1,
                                              const float* __restrict__ W2,
                                              const float* __restrict__ b2,
                                              float* __restrict__ out)
{
    __shared__ float sh[512];
    __shared__ float sy[256];
    __shared__ float red[8][33];
    const int b = blockIdx.x, tid = threadIdx.x;

    sh[tid]       = g_hbuf[((size_t)(0 * 2 + 0) * TB + b) * HH + tid]; // fwd
    sh[256 + tid] = g_hbuf[((size_t)(0 * 2 + 1) * TB + b) * HH + tid]; // bwd
    __syncthreads();

    float a = b1[tid];
    for (int k = 0; k < 512; ++k) a = fmaf(sh[k], W1[(size_t)k * HH + tid], a);
    sy[tid] = fmaxf(a, 0.f);
    __syncthreads();

    const int part = tid >> 5, c = tid & 31;
    float p = 0.f;
#pragma unroll
    for (int kk = 0; kk < 32; ++kk) {
        int k = part * 32 + kk;
        p = fmaf(sy[k], W2[(size_t)k * NCLS + c], p);
    }
    red[part][c] = p;
    __syncthreads();

    if (tid < 32) {
        float l = b2[tid];
#pragma unroll
        for (int q = 0; q < 8; ++q) l += red[q][tid];
        float m = l;
#pragma unroll
        for (int off = 16; off; off >>= 1)
            m = fmaxf(m, __shfl_xor_sync(0xffffffffu, m, off));
        float e = __expf(l - m);
        float ssum = e;
#pragma unroll
        for (int off = 16; off; off >>= 1)
            ssum += __shfl_xor_sync(0xffffffffu, ssum, off);
        out[b * NCLS + tid] = e / ssum;
    }
}

// ============================================================================
extern "C" void kernel_launch(void* const* d_in, const int* in_sizes, int n_in,
                              void* d_out, int out_size)
{
    const void*  tokens = d_in[0];
    const float* emb = (const float*)d_in[1];
    const float* Wf  = (const float*)d_in[2];
    const float* Uf  = (const float*)d_in[3];
    const float* bf  = (const float*)d_in[4];
    const float* Wb  = (const float*)d_in[5];
    const float* Ub  = (const float*)d_in[6];
    const float* bb  = (const float*)d_in[7];
    const float* W1  = (const float*)d_in[8];
    const float* b1  = (const float*)d_in[9];
    const float* W2  = (const float*)d_in[10];
    const float* b2  = (const float*)d_in[11];
    float* out = (float*)d_out;

    k_embW<<<dim3(VV / 32, 4, 2), 256>>>(emb, Wf, Wb);
    k_lstm<<<NCTA, 256>>>(tokens, Uf, bf, Ub, bb);
    k_head<<<TB, 256>>>(W1, b1, W2, b2, out);
}

// round 3
// speedup vs baseline: 1.8038x; 1.8038x over previous
#include <cuda_runtime.h>
#include <cstdint>
#include <cstddef>

#define TB   128   // batch
#define TT   512   // time steps
#define EE   256   // embedding dim
#define HH   256   // hidden dim
#define G4   1024  // 4*H gate width
#define VV   32000 // vocab
#define NCLS 32    // classes
#define NCTA 128   // persistent grid size (<=148 SMs -> co-resident guaranteed)

#define USTRIDE 260            // padded k-stride for U in smem (floats)
#define USMEM_BYTES (128 * USTRIDE * 4)   // 133,120 B dynamic smem

// ---- static device scratch (no allocations allowed) ----
__device__ float g_embW[(size_t)2 * VV * G4];   // [dir][V][4H]  = 262 MB
__device__ float g_hbuf[2 * 2 * TB * HH];       // [buf][dir][b][j] double-buffered h
__device__ int   g_arrive;                      // barrier arrival counter
__device__ int   g_epoch;                       // barrier epoch (monotonic)

__device__ __forceinline__ float sigm(float x) { return 1.0f / (1.0f + __expf(-x)); }

// packed fp32x2 FMA (FFMA2) — bit-exact 2x fp32, sm_100+ PTX
#define FMA_F32X2(d, a, b, c) \
    asm("fma.rn.f32x2 %0, %1, %2, %3;" : "=l"(d) : "l"(a), "l"(b), "l"(c))
#define UNPACK_F32X2(lo, hi, in) \
    asm("mov.b64 {%0, %1}, %2;" : "=f"(lo), "=f"(hi) : "l"(in))
#define PACK_DUP_F32X2(out, x) \
    asm("mov.b64 %0, {%1, %1};" : "=l"(out) : "r"(x))

// ============================================================================
// Kernel 1: embW[d][v][g] = sum_e emb[v][e] * W_d[e][g]
// grid (V/32, 4, 2), block 256. Tile: 32 v-rows x 256 g-cols, K=256.
// FFMA2 pairs over v (lanes = v even/odd); packed (w,w) broadcast operand.
// ============================================================================
__global__ void __launch_bounds__(256) k_embW(const float* __restrict__ emb,
                                              const float* __restrict__ Wf,
                                              const float* __restrict__ Wb)
{
    __shared__ float she[256][36];   // [e][v], v-contiguous, 16B-aligned rows
    const int v0  = blockIdx.x * 32;
    const int gt  = blockIdx.y;
    const int d   = blockIdx.z;
    const int tid = threadIdx.x;
    const float* __restrict__ W = d ? Wb : Wf;

    for (int idx = tid; idx < 32 * 256; idx += 256) {
        int vl = idx >> 8, e = idx & 255;
        she[e][vl] = emb[(size_t)(v0 + vl) * EE + e];   // coalesced over e
    }
    __syncthreads();

    const int g = gt * 256 + tid;
    unsigned long long acc2[16];     // lanes = (v=2q, v=2q+1)
#pragma unroll
    for (int q = 0; q < 16; ++q) acc2[q] = 0ull;

    const float* __restrict__ Wg = W + g;
#pragma unroll 4
    for (int e = 0; e < 256; ++e) {
        float w = Wg[(size_t)e * G4];                   // coalesced 128B/warp
        unsigned long long w2;
        PACK_DUP_F32X2(w2, __float_as_int(w));
#pragma unroll
        for (int p = 0; p < 8; ++p) {
            ulonglong2 a = *(const ulonglong2*)&she[e][p * 4]; // broadcast LDS.128
            FMA_F32X2(acc2[2 * p],     a.x, w2, acc2[2 * p]);
            FMA_F32X2(acc2[2 * p + 1], a.y, w2, acc2[2 * p + 1]);
        }
    }
    size_t base = ((size_t)d * VV + v0) * G4 + g;
#pragma unroll
    for (int q = 0; q < 16; ++q) {
        float lo, hi;
        UNPACK_F32X2(lo, hi, acc2[q]);
        g_embW[base + (size_t)(2 * q)     * G4] = lo;
        g_embW[base + (size_t)(2 * q + 1) * G4] = hi;
    }
}

// ============================================================================
// Kernel 2: persistent bidirectional LSTM recurrence.
// Grid: 128 CTAs = 2 dirs x 8 b-tiles(16) x 8 j-tiles(32 strided gate cols).
// U staged once into dynamic smem, transposed [col][k] (k-contiguous).
// h staged per step into smem [b][k] (k-contiguous).
// FFMA2 pairs over k; horizontal add at the end of the dot product.
// ============================================================================
__global__ void __launch_bounds__(256, 1) k_lstm(const void* __restrict__ tokens_raw,
                                                 const float* __restrict__ Uf,
                                                 const float* __restrict__ bf,
                                                 const float* __restrict__ Ub,
                                                 const float* __restrict__ bb)
{
    extern __shared__ float sU[];    // [128 cols][USTRIDE k]  (132 KB)
    __shared__ float sh_h[16][USTRIDE]; // [b][k] h tile, k-contiguous (16.6 KB)
    __shared__ float sz[16][128];    // z gate tile [b][q*32+jj] (8 KB)
    __shared__ float sc[16][32];     // cell state, CTA-private (2 KB)

    const int id  = blockIdx.x;
    const int jt  = id & 7;
    const int bt  = (id >> 3) & 7;
    const int d   = id >> 6;
    const int tid = threadIdx.x;

    const float* __restrict__ U   = d ? Ub : Uf;
    const float* __restrict__ bia = d ? bb : bf;

    const int b0      = bt * 16;
    const int colbase = jt * 32;
    const int cl      = tid & 127;          // gate-local column 0..127 (q*32+jj)
    const int bh      = tid >> 7;           // batch half 0/1
    const int col     = colbase + (cl & 31) + ((cl >> 5) << 8); // global gate col
    const int bloc0   = bh * 8;

    // ---- runtime token dtype probe: int64 high words are all zero ----
    const int*       __restrict__ t32 = (const int*)tokens_raw;
    const long long* __restrict__ t64 = (const long long*)tokens_raw;
    int probe = 0;
#pragma unroll
    for (int i = 1; i < 64; i += 2) probe |= t32[i];
    const bool tok32 = (probe != 0);

    // ---- one-time U stage: sU[cl][k] = U[k][col] (transposed) ----
    {
        const int k0 = bh * 128;
        for (int k = k0; k < k0 + 128; ++k)
            sU[cl * USTRIDE + k] = U[(size_t)k * G4 + col];   // coalesced over cl
    }
    for (int idx = tid; idx < 512; idx += 256) sc[idx >> 5][idx & 31] = 0.f;
    const int epoch0 = *(volatile int*)&g_epoch;  // stable between launches
    __syncthreads();

    const float bcol = bia[col];
    const float* __restrict__ Urow = &sU[cl * USTRIDE];

    for (int s = 0; s < TT; ++s) {
        const int tstep = d ? (TT - 1 - s) : s;
        float acc[8];
        unsigned long long acc2[8];
#pragma unroll
        for (int r = 0; r < 8; ++r) acc2[r] = 0ull;

        if (s > 0) {   // h_0 = 0 -> skip recurrent GEMM at step 0
            const int rb = s & 1;   // step s-1 wrote buffer s&1
            const float* __restrict__ hsrc =
                g_hbuf + ((size_t)(rb * 2 + d) * TB + b0) * HH;
            // stage 16 b x 256 k, float4, coalesced
#pragma unroll
            for (int i = 0; i < 4; ++i) {
                int idx = tid + i * 256;            // 0..1023 float4 slots
                int bl = idx >> 6, kq = idx & 63;
                *(float4*)&sh_h[bl][kq * 4] =
                    *(const float4*)&hsrc[bl * HH + kq * 4];
            }
            __syncthreads();

#pragma unroll 2
            for (int kc = 0; kc < 64; ++kc) {       // 4 k per chunk
                ulonglong2 u = *(const ulonglong2*)&Urow[kc * 4]; // (k,k+1),(k+2,k+3)
#pragma unroll
                for (int r = 0; r < 8; ++r) {
                    ulonglong2 hv = *(const ulonglong2*)&sh_h[bloc0 + r][kc * 4]; // broadcast
                    FMA_F32X2(acc2[r], hv.x, u.x, acc2[r]);
                    FMA_F32X2(acc2[r], hv.y, u.y, acc2[r]);
                }
            }
        }
#pragma unroll
        for (int r = 0; r < 8; ++r) {
            float lo, hi;
            UNPACK_F32X2(lo, hi, acc2[r]);
            acc[r] = lo + hi;
        }

        // add gathered input projection + bias, stage z in shared
#pragma unroll
        for (int r = 0; r < 8; ++r) {
            int b  = b0 + bloc0 + r;
            int tk = tok32 ? t32[b * TT + tstep] : (int)t64[b * TT + tstep];
            float xw = g_embW[((size_t)d * VV + tk) * G4 + col];
            sz[bloc0 + r][cl] = acc[r] + xw + bcol;
        }
        __syncthreads();

        // gate update: 512 cells, 2 per thread; c stays in smem
#pragma unroll
        for (int half = 0; half < 2; ++half) {
            int cell = tid + half * 256;
            int bl = cell >> 5, jj = cell & 31;
            float zi = sz[bl][jj];
            float zf = sz[bl][32 + jj];
            float zg = sz[bl][64 + jj];
            float zo = sz[bl][96 + jj];
            float c  = sc[bl][jj];
            float cn = sigm(zf) * c + sigm(zi) * tanhf(zg);
            float h  = sigm(zo) * tanhf(cn);
            sc[bl][jj] = cn;
            g_hbuf[((size_t)(((s + 1) & 1) * 2 + d) * TB + (b0 + bl)) * HH
                   + colbase + jj] = h;
        }
        __syncthreads();

        // ---- grid barrier (sense/epoch; all 128 CTAs co-resident) ----
        if (tid == 0) {
            __threadfence();
            int a = atomicAdd(&g_arrive, 1);
            if (a == NCTA - 1) {
                atomicExch(&g_arrive, 0);
                __threadfence();
                atomicAdd(&g_epoch, 1);
            } else {
                const int target = epoch0 + s + 1;
                while ((*(volatile int*)&g_epoch) - target < 0) { }
            }
            __threadfence();
        }
        __syncthreads();
    }
}

// ============================================================================
// Kernel 3: head. One block per batch row.
// h_cat[512] -> relu(dense 256) -> logits 32 -> softmax.
// Final h lives in g_hbuf buffer (511+1)&1 = 0.
// ============================================================================
__global__ void __launch_bounds__(256) k_head(const float* __restrict__ W1,
                                              const float* __restrict__ b1,
                                              const float* __restrict__ W2,
                                              const float* __restrict__ b2,
                                              float* __restrict__ out)
{
    __shared__ float sh[512];
    __shared__ float sy[256];
    __shared__ float red[8][33];
    const int b = blockIdx.x, tid = threadIdx.x;

    sh[tid]       = g_hbuf[((size_t)0 * TB + b) * HH + tid]; // fwd (buf0, dir0)
    sh[256 + tid] = g_hbuf[((size_t)1 * TB + b) * HH + tid]; // bwd (buf0, dir1)
    __syncthreads();

    float a = b1[tid];
    for (int k = 0; k < 512; ++k) a = fmaf(sh[k], W1[(size_t)k * HH + tid], a);
    sy[tid] = fmaxf(a, 0.f);
    __syncthreads();

    const int part = tid >> 5, c = tid & 31;
    float p = 0.f;
#pragma unroll
    for (int kk = 0; kk < 32; ++kk) {
        int k = part * 32 + kk;
        p = fmaf(sy[k], W2[(size_t)k * NCLS + c], p);
    }
    red[part][c] = p;
    __syncthreads();

    if (tid < 32) {
        float l = b2[tid];
#pragma unroll
        for (int q = 0; q < 8; ++q) l += red[q][tid];
        float m = l;
#pragma unroll
        for (int off = 16; off; off >>= 1)
            m = fmaxf(m, __shfl_xor_sync(0xffffffffu, m, off));
        float e = __expf(l - m);
        float ssum = e;
#pragma unroll
        for (int off = 16; off; off >>= 1)
            ssum += __shfl_xor_sync(0xffffffffu, ssum, off);
        out[b * NCLS + tid] = e / ssum;
    }
}

// ============================================================================
extern "C" void kernel_launch(void* const* d_in, const int* in_sizes, int n_in,
                              void* d_out, int out_size)
{
    const void*  tokens = d_in[0];
    const float* emb = (const float*)d_in[1];
    const float* Wf  = (const float*)d_in[2];
    const float* Uf  = (const float*)d_in[3];
    const float* bf  = (const float*)d_in[4];
    const float* Wb  = (const float*)d_in[5];
    const float* Ub  = (const float*)d_in[6];
    const float* bb  = (const float*)d_in[7];
    const float* W1  = (const float*)d_in[8];
    const float* b1  = (const float*)d_in[9];
    const float* W2  = (const float*)d_in[10];
    const float* b2  = (const float*)d_in[11];
    float* out = (float*)d_out;

    cudaFuncSetAttribute(k_lstm, cudaFuncAttributeMaxDynamicSharedMemorySize,
                         USMEM_BYTES);

    k_embW<<<dim3(VV / 32, 4, 2), 256>>>(emb, Wf, Wb);
    k_lstm<<<NCTA, 256, USMEM_BYTES>>>(tokens, Uf, bf, Ub, bb);
    k_head<<<TB, 256>>>(W1, b1, W2, b2, out);
}